// round 7
// baseline (speedup 1.0000x reference)
#include <cuda_runtime.h>
#include <cstdint>

#define NHITS 80000
#define KOBJ  512
#define NREP  32
#define KCHUNK 128
#define NCHUNK (KOBJ / KCHUNK)     // 4
#define EPSF  1e-9f

#define NBX1 79                     // ceil(80000/1024)
#define NBX3 313                    // ceil(80000/256)
#define TOTAL_P3_BLOCKS (NBX3 * NCHUNK)          // 1252
#define SCRATCH_TOT (NREP * KOBJ)                // 16384
#define ZERO_PER_BLOCK ((SCRATCH_TOT + TOTAL_P3_BLOCKS - 1) / TOTAL_P3_BLOCKS) // 14

// ---------------- device scratch (zero at load; re-zeroed by phase3 each run)
__device__ unsigned long long g_packed[NREP][KOBJ];
__device__ int    g_cnt[NREP][KOBJ];
__device__ float  g_num[NREP][KOBJ];
__device__ float  g_den[NREP][KOBJ];
__device__ float  g_q[NHITS];
__device__ float4 g_pA[KOBJ / 2];   // (m2ox_j, m2ox_j1, m2oy_j, m2oy_j1)
__device__ float4 g_pB[KOBJ / 2];   // (ozeps_j, ozeps_j1, w_j, w_j1)
__device__ float  g_attw[KOBJ];
__device__ float  g_wsum[8];        // per-chunk sum of repulsion weights (NCHUNK<=8)
__device__ float  g_scal[8];        // 0:noise_b 1:noise_cnt 2:cc 3:pot 4:beta+pay 6:nobj
__device__ unsigned g_ticket;

// ---------------- helpers ----------------
__device__ __forceinline__ float softclipf(float x, float s) {
    float y = x / s;
    y = (y > 1.0f) ? __logf(y + 1.0f) : y;
    return y * s;
}
__device__ __forceinline__ float huberf(float x, float d) {
    float ax = fabsf(x);
    return (ax < d) ? x * x : d * d + 2.0f * d * (ax - d);
}
__device__ __forceinline__ float warpSum(float v) {
    #pragma unroll
    for (int o = 16; o > 0; o >>= 1) v += __shfl_down_sync(0xffffffffu, v, o);
    return v;
}
__device__ __forceinline__ float sqrt_approx(float x) {
    float r;
    asm("sqrt.approx.f32 %0, %1;" : "=f"(r) : "f"(x));
    return r;
}
__device__ __forceinline__ float fast_atanh(float b) {
    return 0.5f * __logf(__fdividef(1.0f + b, 1.0f - b));
}
// packed f32x2 helpers
__device__ __forceinline__ unsigned long long pk2(float lo, float hi) {
    unsigned long long r;
    asm("mov.b64 %0, {%1, %2};" : "=l"(r) : "f"(lo), "f"(hi));
    return r;
}
__device__ __forceinline__ void unpk2(unsigned long long v, float& lo, float& hi) {
    asm("mov.b64 {%0, %1}, %2;" : "=f"(lo), "=f"(hi) : "l"(v));
}
__device__ __forceinline__ unsigned long long fma2_(unsigned long long a,
                                                    unsigned long long b,
                                                    unsigned long long c) {
    unsigned long long r;
    asm("fma.rn.f32x2 %0, %1, %2, %3;" : "=l"(r) : "l"(a), "l"(b), "l"(c));
    return r;
}
__device__ __forceinline__ unsigned long long add2_(unsigned long long a,
                                                    unsigned long long b) {
    unsigned long long r;
    asm("add.rn.f32x2 %0, %1, %2;" : "=l"(r) : "l"(a), "l"(b));
    return r;
}

// ---------------- phase 1: per-hit pass (1024-thread blocks) ----------------
__global__ void __launch_bounds__(1024) k_phase1(
    const float* __restrict__ pb, const float2* __restrict__ cc,
    const float* __restrict__ pE, const float2* __restrict__ pPos,
    const float* __restrict__ pT, const float2* __restrict__ pId2,
    const int*   __restrict__ tIdx, const float* __restrict__ tE,
    const float2* __restrict__ tPos, const float* __restrict__ tT)
{
    int n = blockIdx.x * 1024 + threadIdx.x;
    int rep = ((blockIdx.x << 3) | (threadIdx.x >> 7)) & (NREP - 1);
    float nb = 0.0f, ncnt = 0.0f, ccs = 0.0f;
    if (n < NHITS) {
        float b = fminf(fmaxf(pb[n], 1e-6f), 1.0f - 1e-6f);
        float at = fast_atanh(b);
        float q = fmaf(at, at, 0.1f);
        g_q[n] = q;
        float2 c = cc[n];
        ccs = fmaf(c.x, c.x, c.y * c.y);
        int t = tIdx[n];
        if (t >= 0) {
            atomicAdd(&g_cnt[rep][t], 1);
            unsigned long long pk =
                ((unsigned long long)__float_as_uint(b) << 32) |
                (unsigned long long)(0xFFFFFFFFu - (unsigned)n);
            atomicMax(&g_packed[rep][t], pk);
            float te = tE[n];
            float ed = fabsf(te - pE[n]);
            float le = 10.0f * __expf(-0.1f * ed * ed) + 0.01f * ed;
            le = softclipf(le, 10.0f);
            float2 tp = tPos[n], pp = pPos[n];
            float dpx = tp.x - pp.x, dpy = tp.y - pp.y;
            float d2p = fmaf(dpx, dpx, dpy * dpy);
            float pl = softclipf(huberf(sqrt_approx(fmaf(d2p, 0.01f, 0.01f)), 10.0f), 3.0f);
            float tl = softclipf(huberf(tT[n] - pT[n], 2.0f), 6.0f);
            float2 i0 = pId2[3 * n], i1 = pId2[3 * n + 1], i2 = pId2[3 * n + 2];
            float cls = i0.x * i0.x + i0.y * i0.y + i1.x * i1.x
                      + i1.y * i1.y + i2.x * i2.x + i2.y * i2.y;
            cls *= (1e-8f / 6.0f);
            float payload = le + pl + tl + cls;
            float ew = (te > 10.0f) ? 1.0f : fmaxf((te - 0.5f) * (1.0f / 9.5f), 0.0f);
            float pw = b * ew;
            atomicAdd(&g_num[rep][t], payload * pw);
            atomicAdd(&g_den[rep][t], pw);
        } else {
            nb = b; ncnt = 1.0f;
        }
    }
    __shared__ float sr[3][32];
    float w0 = warpSum(nb), w1 = warpSum(ncnt), w2 = warpSum(ccs);
    int lane = threadIdx.x & 31, wid = threadIdx.x >> 5;
    if (lane == 0) { sr[0][wid] = w0; sr[1][wid] = w1; sr[2][wid] = w2; }
    __syncthreads();
    if (wid == 0) {
        float v0 = sr[0][lane];
        float v1 = sr[1][lane];
        float v2 = sr[2][lane];
        v0 = warpSum(v0); v1 = warpSum(v1); v2 = warpSum(v2);
        if (lane == 0) {
            if (v1 != 0.0f || v0 != 0.0f) {
                atomicAdd(&g_scal[0], v0);
                atomicAdd(&g_scal[1], v1);
            }
            atomicAdd(&g_scal[2], v2);
        }
    }
}

// ---------------- phase 2: reduce replicas, object pairs, vector loads -----
__global__ void __launch_bounds__(128) k_phase2(const float2* __restrict__ cc) {
    int t = blockIdx.x * 128 + threadIdx.x;   // 0..255, objects 2t, 2t+1
    int k0 = 2 * t;
    int c0 = 0, c1 = 0;
    float n0 = 0.0f, n1 = 0.0f, d0 = 0.0f, d1 = 0.0f;
    unsigned long long p0 = 0ull, p1 = 0ull;
    #pragma unroll
    for (int r = 0; r < NREP; r++) {
        int2 cv = *(const int2*)&g_cnt[r][k0];
        float2 nv = *(const float2*)&g_num[r][k0];
        float2 dv = *(const float2*)&g_den[r][k0];
        ulonglong2 pv = *(const ulonglong2*)&g_packed[r][k0];
        c0 += cv.x; c1 += cv.y;
        n0 += nv.x; n1 += nv.y;
        d0 += dv.x; d1 += dv.y;
        p0 = (pv.x > p0) ? pv.x : p0;
        p1 = (pv.y > p1) ? pv.y : p1;
    }
    float part = 0.0f, nob = 0.0f, wsum = 0.0f;
    float4 A = make_float4(0.0f, 0.0f, 0.0f, 0.0f);
    float4 B = make_float4(1e6f, 1e6f, 0.0f, 0.0f);
    float aw0 = 0.0f, aw1 = 0.0f;
    if (c0 > 0) {
        float betaA = __uint_as_float((unsigned)(p0 >> 32));
        unsigned alpha = 0xFFFFFFFFu - (unsigned)(p0 & 0xFFFFFFFFull);
        float2 c = cc[alpha];
        float at = fast_atanh(betaA);
        float qa = fmaf(at, at, 0.1f);
        A.x = -2.0f * c.x;  A.z = -2.0f * c.y;
        B.x = fmaf(c.x, c.x, c.y * c.y) + 1e-6f;
        B.z = qa / ((float)NHITS - (float)c0 + EPSF);
        aw0 = qa / ((float)c0 + EPSF);
        part += (1.0f - betaA) + n0 / (d0 + EPSF);
        nob += 1.0f; wsum += B.z;
    }
    if (c1 > 0) {
        float betaA = __uint_as_float((unsigned)(p1 >> 32));
        unsigned alpha = 0xFFFFFFFFu - (unsigned)(p1 & 0xFFFFFFFFull);
        float2 c = cc[alpha];
        float at = fast_atanh(betaA);
        float qa = fmaf(at, at, 0.1f);
        A.y = -2.0f * c.x;  A.w = -2.0f * c.y;
        B.y = fmaf(c.x, c.x, c.y * c.y) + 1e-6f;
        B.w = qa / ((float)NHITS - (float)c1 + EPSF);
        aw1 = qa / ((float)c1 + EPSF);
        part += (1.0f - betaA) + n1 / (d1 + EPSF);
        nob += 1.0f; wsum += B.w;
    }
    g_pA[t] = A;
    g_pB[t] = B;
    g_attw[k0] = aw0;
    g_attw[k0 + 1] = aw1;
    // chunk = k>>7; thread t covers k=2t..2t+1 -> chunk = t>>6 (warp-uniform pairs)
    float ws = warpSum(wsum);
    float wp = warpSum(part);
    float wn = warpSum(nob);
    int lane = threadIdx.x & 31;
    if (lane == 0) {
        atomicAdd(&g_wsum[(blockIdx.x * 128 + (threadIdx.x & ~31)) >> 6], ws);
        atomicAdd(&g_scal[4], wp);
        atomicAdd(&g_scal[6], wn);
    }
}

// ---------------- phase 3: dense N x KCHUNK (packed) + zero + finalize -----
__global__ void __launch_bounds__(256) k_phase3(
    const float2* __restrict__ cc, const int* __restrict__ tIdx,
    float* __restrict__ out)
{
    __shared__ float4 sA[KCHUNK / 2];
    __shared__ float4 sB[KCHUNK / 2];
    const int kbase = blockIdx.y * KCHUNK;

    // hoist hit loads before the barrier
    int n = blockIdx.x * blockDim.x + threadIdx.x;
    int nc = (n < NHITS) ? n : 0;
    float2 c = cc[nc];
    float q = g_q[nc];
    int t = tIdx[nc];
    float wsum_chunk = g_wsum[blockIdx.y];

    if (threadIdx.x < KCHUNK / 2) {
        sA[threadIdx.x] = g_pA[kbase / 2 + threadIdx.x];
        sB[threadIdx.x] = g_pB[kbase / 2 + threadIdx.x];
    }
    // distributed re-zero of the replicated scratch
    {
        int lin = blockIdx.y * NBX3 + blockIdx.x;
        if (threadIdx.x < ZERO_PER_BLOCK) {
            int idx = lin * ZERO_PER_BLOCK + threadIdx.x;
            if (idx < SCRATCH_TOT) {
                ((int*)g_cnt)[idx] = 0;
                ((float*)g_num)[idx] = 0.0f;
                ((float*)g_den)[idx] = 0.0f;
                ((unsigned long long*)g_packed)[idx] = 0ull;
            }
        }
    }
    __syncthreads();

    float res = 0.0f;
    if (n < NHITS) {
        float x = c.x, y = c.y;
        float h = fmaf(x, x, y * y);
        unsigned long long XX = pk2(x, x), YY = pk2(y, y), HH = pk2(h, h);
        float acc0 = 0.0f, acc1 = 0.0f;
        const ulonglong2* A2 = (const ulonglong2*)sA;
        const ulonglong2* B2 = (const ulonglong2*)sB;
        #pragma unroll 8
        for (int p = 0; p < KCHUNK / 2; p += 2) {
            {
                ulonglong2 A = A2[p];
                ulonglong2 B = B2[p];
                unsigned long long tt = fma2_(A.y, YY, B.x);
                tt = fma2_(A.x, XX, tt);
                tt = add2_(tt, HH);
                float d2a, d2b; unpk2(tt, d2a, d2b);
                float da = sqrt_approx(d2a), db = sqrt_approx(d2b);
                float wa, wb; unpk2(B.y, wa, wb);
                acc0 = fmaf(wa, fminf(da, 1.0f), acc0);
                acc0 = fmaf(wb, fminf(db, 1.0f), acc0);
            }
            {
                ulonglong2 A = A2[p + 1];
                ulonglong2 B = B2[p + 1];
                unsigned long long tt = fma2_(A.y, YY, B.x);
                tt = fma2_(A.x, XX, tt);
                tt = add2_(tt, HH);
                float d2a, d2b; unpk2(tt, d2a, d2b);
                float da = sqrt_approx(d2a), db = sqrt_approx(d2b);
                float wa, wb; unpk2(B.y, wa, wb);
                acc1 = fmaf(wa, fminf(da, 1.0f), acc1);
                acc1 = fmaf(wb, fminf(db, 1.0f), acc1);
            }
        }
        // sum_k w*relu(1-d) = Wsum_chunk - sum_k w*min(d,1)
        res = (wsum_chunk - (acc0 + acc1)) * q;
        if (t >= kbase && t < kbase + KCHUNK) {
            int j = t - kbase;
            int pr = j >> 1, hf = j & 1;
            float4 Af = sA[pr], Bf = sB[pr];
            float m2ox = hf ? Af.y : Af.x;
            float m2oy = hf ? Af.w : Af.z;
            float w    = hf ? Bf.w : Bf.z;
            float dx = fmaf(0.5f, m2ox, c.x);
            float dy = fmaf(0.5f, m2oy, c.y);
            float d2n = fmaf(dx, dx, dy * dy);
            float d = sqrt_approx(d2n + 1e-6f);
            res -= fmaxf(1.0f - d, 0.0f) * w * q;
            res = fmaf(d2n * g_attw[t], q, res);
        }
    }
    __shared__ float sr[8];
    float wv = warpSum(res);
    int lane = threadIdx.x & 31, wid = threadIdx.x >> 5;
    if (lane == 0) sr[wid] = wv;
    __syncthreads();
    __shared__ bool isLast;
    if (threadIdx.x == 0) isLast = false;
    if (wid == 0) {
        float v = (lane < 8) ? sr[lane] : 0.0f;
        v = warpSum(v);
        if (lane == 0) {
            atomicAdd(&g_scal[3], v);
            __threadfence();
            unsigned tk = atomicAdd(&g_ticket, 1u);
            isLast = (tk == (unsigned)(TOTAL_P3_BLOCKS - 1));
        }
    }
    __syncthreads();
    if (isLast) {
        if (threadIdx.x == 0) {
            float inv = 1.0f / (g_scal[6] + EPSF);
            float total = (g_scal[3] + g_scal[4]) * inv
                        + g_scal[0] / (g_scal[1] + EPSF)
                        + 0.001f * g_scal[2] * (1.0f / ((float)NHITS * 2.0f));
            out[0] = total;
            g_ticket = 0;
        }
        __syncthreads();
        if (threadIdx.x < 8) {
            g_scal[threadIdx.x] = 0.0f;
            g_wsum[threadIdx.x] = 0.0f;
        }
    }
}

// ---------------- launch ----------------
extern "C" void kernel_launch(void* const* d_in, const int* in_sizes, int n_in,
                              void* d_out, int out_size)
{
    const float*  pb   = (const float*) d_in[0];
    const float2* cc   = (const float2*)d_in[1];
    const float*  pE   = (const float*) d_in[2];
    const float2* pPos = (const float2*)d_in[3];
    const float*  pT   = (const float*) d_in[4];
    const float2* pId2 = (const float2*)d_in[5];
    const int*    tIdx = (const int*)   d_in[6];
    const float*  tE   = (const float*) d_in[7];
    const float2* tPos = (const float2*)d_in[8];
    const float*  tT   = (const float*) d_in[9];
    float* out = (float*)d_out;

    k_phase1<<<NBX1, 1024>>>(pb, cc, pE, pPos, pT, pId2, tIdx, tE, tPos, tT);
    k_phase2<<<2, 128>>>(cc);
    dim3 g3(NBX3, NCHUNK);
    k_phase3<<<g3, 256>>>(cc, tIdx, out);
}

// round 8
// speedup vs baseline: 1.1220x; 1.1220x over previous
#include <cuda_runtime.h>
#include <cstdint>

#define NHITS 80000
#define KOBJ  512
#define NREP  32
#define KCHUNK 64
#define NCHUNK (KOBJ / KCHUNK)     // 8
#define EPSF  1e-9f

#define NBX1 157                    // ceil(80000/512), 2 hits per thread
#define NBX3 313                    // ceil(80000/256)
#define TOTAL_P3_BLOCKS (NBX3 * NCHUNK)          // 2504
#define SCRATCH_TOT (NREP * KOBJ)                // 16384
#define ZERO_PER_BLOCK ((SCRATCH_TOT + TOTAL_P3_BLOCKS - 1) / TOTAL_P3_BLOCKS) // 7

// ---------------- device scratch (zero at load; re-zeroed by phase3 each run)
__device__ unsigned long long g_packed[NREP][KOBJ];
__device__ int    g_cnt[NREP][KOBJ];
__device__ float  g_num[NREP][KOBJ];
__device__ float  g_den[NREP][KOBJ];
__device__ float  g_q[NHITS];
__device__ float4 g_pA[KOBJ / 2];   // (m2ox_j, m2ox_j1, m2oy_j, m2oy_j1)
__device__ float4 g_pB[KOBJ / 2];   // (ozeps_j, ozeps_j1, w_j, w_j1)
__device__ float  g_attw[KOBJ];
__device__ float  g_wsum[NCHUNK];   // per-chunk sum of repulsion weights
__device__ float  g_scal[8];        // 0:noise_b 1:noise_cnt 2:cc 3:pot 4:beta+pay 6:nobj
__device__ unsigned g_ticket1;
__device__ unsigned g_ticket3;

// ---------------- helpers ----------------
__device__ __forceinline__ float softclipf(float x, float s) {
    float y = x / s;
    y = (y > 1.0f) ? __logf(y + 1.0f) : y;
    return y * s;
}
__device__ __forceinline__ float huberf(float x, float d) {
    float ax = fabsf(x);
    return (ax < d) ? x * x : d * d + 2.0f * d * (ax - d);
}
__device__ __forceinline__ float warpSum(float v) {
    #pragma unroll
    for (int o = 16; o > 0; o >>= 1) v += __shfl_down_sync(0xffffffffu, v, o);
    return v;
}
__device__ __forceinline__ float sqrt_approx(float x) {
    float r;
    asm("sqrt.approx.f32 %0, %1;" : "=f"(r) : "f"(x));
    return r;
}
__device__ __forceinline__ float fast_atanh(float b) {
    return 0.5f * __logf(__fdividef(1.0f + b, 1.0f - b));
}
// packed f32x2 helpers
__device__ __forceinline__ unsigned long long pk2(float lo, float hi) {
    unsigned long long r;
    asm("mov.b64 %0, {%1, %2};" : "=l"(r) : "f"(lo), "f"(hi));
    return r;
}
__device__ __forceinline__ void unpk2(unsigned long long v, float& lo, float& hi) {
    asm("mov.b64 {%0, %1}, %2;" : "=f"(lo), "=f"(hi) : "l"(v));
}
__device__ __forceinline__ unsigned long long fma2_(unsigned long long a,
                                                    unsigned long long b,
                                                    unsigned long long c) {
    unsigned long long r;
    asm("fma.rn.f32x2 %0, %1, %2, %3;" : "=l"(r) : "l"(a), "l"(b), "l"(c));
    return r;
}
__device__ __forceinline__ unsigned long long add2_(unsigned long long a,
                                                    unsigned long long b) {
    unsigned long long r;
    asm("add.rn.f32x2 %0, %1, %2;" : "=l"(r) : "l"(a), "l"(b));
    return r;
}

// per-hit payload path (object hits only)
__device__ __forceinline__ void hit_obj(
    int n, int rep, int t, float b,
    float te, float pe, float tt_, float pt_,
    float2 tp, float2 pp, const float4* __restrict__ pId4_lo,
    float cls)
{
    atomicAdd(&g_cnt[rep][t], 1);
    unsigned long long pk =
        ((unsigned long long)__float_as_uint(b) << 32) |
        (unsigned long long)(0xFFFFFFFFu - (unsigned)n);
    atomicMax(&g_packed[rep][t], pk);
    float ed = fabsf(te - pe);
    float le = 10.0f * __expf(-0.1f * ed * ed) + 0.01f * ed;
    le = softclipf(le, 10.0f);
    float dpx = tp.x - pp.x, dpy = tp.y - pp.y;
    float d2p = fmaf(dpx, dpx, dpy * dpy);
    float pl = softclipf(huberf(sqrt_approx(fmaf(d2p, 0.01f, 0.01f)), 10.0f), 3.0f);
    float tl = softclipf(huberf(tt_ - pt_, 2.0f), 6.0f);
    float payload = le + pl + tl + cls;
    float ew = (te > 10.0f) ? 1.0f : fmaxf((te - 0.5f) * (1.0f / 9.5f), 0.0f);
    float pw = b * ew;
    atomicAdd(&g_num[rep][t], payload * pw);
    atomicAdd(&g_den[rep][t], pw);
}

// ---------------- phase 1: per-hit pass (2 hits/thread) + fused phase 2 ----
__global__ void __launch_bounds__(256) k_phase1(
    const float2* __restrict__ pb2, const float4* __restrict__ cc4,
    const float2* __restrict__ pE2, const float4* __restrict__ pPos4,
    const float2* __restrict__ pT2, const float4* __restrict__ pId4,
    const int2*   __restrict__ tIdx2, const float2* __restrict__ tE2,
    const float4* __restrict__ tPos4, const float2* __restrict__ tT2,
    const float2* __restrict__ cc)
{
    int m = blockIdx.x * 256 + threadIdx.x;      // pair index: hits 2m, 2m+1
    int rep = ((blockIdx.x << 1) | (threadIdx.x >> 7)) & (NREP - 1);
    float nb = 0.0f, ncnt = 0.0f, ccs = 0.0f;
    if (2 * m < NHITS) {       // NHITS even -> full pairs
        // issue all loads up front (MLP)
        float2 bb = pb2[m];
        float4 cv = cc4[m];
        int2   tv = tIdx2[m];
        float2 te = tE2[m];
        float2 pe = pE2[m];
        float4 tp = tPos4[m];
        float4 pp = pPos4[m];
        float2 tt_ = tT2[m];
        float2 pt_ = pT2[m];
        float4 i0 = pId4[3 * m], i1 = pId4[3 * m + 1], i2 = pId4[3 * m + 2];

        ccs = fmaf(cv.x, cv.x, cv.y * cv.y) + fmaf(cv.z, cv.z, cv.w * cv.w);

        // hit 2m
        {
            float b = fminf(fmaxf(bb.x, 1e-6f), 1.0f - 1e-6f);
            float at = fast_atanh(b);
            g_q[2 * m] = fmaf(at, at, 0.1f);
            float cls = (i0.x * i0.x + i0.y * i0.y + i0.z * i0.z
                       + i0.w * i0.w + i1.x * i1.x + i1.y * i1.y) * (1e-8f / 6.0f);
            if (tv.x >= 0) {
                hit_obj(2 * m, rep, tv.x, b, te.x, pe.x, tt_.x, pt_.x,
                        make_float2(tp.x, tp.y), make_float2(pp.x, pp.y),
                        pId4, cls);
            } else { nb += b; ncnt += 1.0f; }
        }
        // hit 2m+1
        {
            float b = fminf(fmaxf(bb.y, 1e-6f), 1.0f - 1e-6f);
            float at = fast_atanh(b);
            g_q[2 * m + 1] = fmaf(at, at, 0.1f);
            float cls = (i1.z * i1.z + i1.w * i1.w + i2.x * i2.x
                       + i2.y * i2.y + i2.z * i2.z + i2.w * i2.w) * (1e-8f / 6.0f);
            if (tv.y >= 0) {
                hit_obj(2 * m + 1, rep, tv.y, b, te.y, pe.y, tt_.y, pt_.y,
                        make_float2(tp.z, tp.w), make_float2(pp.z, pp.w),
                        pId4, cls);
            } else { nb += b; ncnt += 1.0f; }
        }
    }
    __shared__ float sr[3][8];
    float w0 = warpSum(nb), w1 = warpSum(ncnt), w2 = warpSum(ccs);
    int lane = threadIdx.x & 31, wid = threadIdx.x >> 5;
    if (lane == 0) { sr[0][wid] = w0; sr[1][wid] = w1; sr[2][wid] = w2; }
    __syncthreads();
    if (wid == 0) {
        float v0 = (lane < 8) ? sr[0][lane] : 0.0f;
        float v1 = (lane < 8) ? sr[1][lane] : 0.0f;
        float v2 = (lane < 8) ? sr[2][lane] : 0.0f;
        v0 = warpSum(v0); v1 = warpSum(v1); v2 = warpSum(v2);
        if (lane == 0) {
            if (v1 != 0.0f || v0 != 0.0f) {
                atomicAdd(&g_scal[0], v0);
                atomicAdd(&g_scal[1], v1);
            }
            atomicAdd(&g_scal[2], v2);
        }
    }

    // ---- fused phase 2: last block reduces replicas & builds object data ----
    __shared__ bool lastB;
    if (threadIdx.x == 0) {
        __threadfence();
        unsigned tk = atomicAdd(&g_ticket1, 1u);
        lastB = (tk == (unsigned)(NBX1 - 1));
        if (lastB) g_ticket1 = 0;
    }
    __syncthreads();
    if (!lastB) return;

    int t = threadIdx.x;           // 0..255, objects 2t, 2t+1
    int k0 = 2 * t;
    int c0 = 0, c1 = 0;
    float n0 = 0.0f, n1 = 0.0f, d0 = 0.0f, d1 = 0.0f;
    unsigned long long p0 = 0ull, p1 = 0ull;
    #pragma unroll
    for (int r = 0; r < NREP; r++) {
        int2 cvv = *(const int2*)&g_cnt[r][k0];
        float2 nv = *(const float2*)&g_num[r][k0];
        float2 dv = *(const float2*)&g_den[r][k0];
        ulonglong2 pv = *(const ulonglong2*)&g_packed[r][k0];
        c0 += cvv.x; c1 += cvv.y;
        n0 += nv.x; n1 += nv.y;
        d0 += dv.x; d1 += dv.y;
        p0 = (pv.x > p0) ? pv.x : p0;
        p1 = (pv.y > p1) ? pv.y : p1;
    }
    float part = 0.0f, nob = 0.0f, wsum = 0.0f;
    float4 A = make_float4(0.0f, 0.0f, 0.0f, 0.0f);
    float4 B = make_float4(1e6f, 1e6f, 0.0f, 0.0f);
    float aw0 = 0.0f, aw1 = 0.0f;
    if (c0 > 0) {
        float betaA = __uint_as_float((unsigned)(p0 >> 32));
        unsigned alpha = 0xFFFFFFFFu - (unsigned)(p0 & 0xFFFFFFFFull);
        float2 c = cc[alpha];
        float at = fast_atanh(betaA);
        float qa = fmaf(at, at, 0.1f);
        A.x = -2.0f * c.x;  A.z = -2.0f * c.y;
        B.x = fmaf(c.x, c.x, c.y * c.y) + 1e-6f;
        B.z = qa / ((float)NHITS - (float)c0 + EPSF);
        aw0 = qa / ((float)c0 + EPSF);
        part += (1.0f - betaA) + n0 / (d0 + EPSF);
        nob += 1.0f; wsum += B.z;
    }
    if (c1 > 0) {
        float betaA = __uint_as_float((unsigned)(p1 >> 32));
        unsigned alpha = 0xFFFFFFFFu - (unsigned)(p1 & 0xFFFFFFFFull);
        float2 c = cc[alpha];
        float at = fast_atanh(betaA);
        float qa = fmaf(at, at, 0.1f);
        A.y = -2.0f * c.x;  A.w = -2.0f * c.y;
        B.y = fmaf(c.x, c.x, c.y * c.y) + 1e-6f;
        B.w = qa / ((float)NHITS - (float)c1 + EPSF);
        aw1 = qa / ((float)c1 + EPSF);
        part += (1.0f - betaA) + n1 / (d1 + EPSF);
        nob += 1.0f; wsum += B.w;
    }
    g_pA[t] = A;
    g_pB[t] = B;
    g_attw[k0] = aw0;
    g_attw[k0 + 1] = aw1;
    // chunk index for objects 2t,2t+1 with KCHUNK=64: (2t)>>6 = t>>5 (warp-uniform)
    float ws = warpSum(wsum);
    float wp = warpSum(part);
    float wn = warpSum(nob);
    if ((threadIdx.x & 31) == 0) {
        atomicAdd(&g_wsum[threadIdx.x >> 5], ws);
        atomicAdd(&g_scal[4], wp);
        atomicAdd(&g_scal[6], wn);
    }
}

// ---------------- phase 3: dense N x KCHUNK (packed) + zero + finalize -----
__global__ void __launch_bounds__(256) k_phase3(
    const float2* __restrict__ cc, const int* __restrict__ tIdx,
    float* __restrict__ out)
{
    __shared__ float4 sA[KCHUNK / 2];
    __shared__ float4 sB[KCHUNK / 2];
    const int kbase = blockIdx.y * KCHUNK;
    if (threadIdx.x < KCHUNK / 2) {
        sA[threadIdx.x] = g_pA[kbase / 2 + threadIdx.x];
        sB[threadIdx.x] = g_pB[kbase / 2 + threadIdx.x];
    }
    // distributed re-zero of the replicated scratch
    {
        int lin = blockIdx.y * NBX3 + blockIdx.x;
        if (threadIdx.x < ZERO_PER_BLOCK) {
            int idx = lin * ZERO_PER_BLOCK + threadIdx.x;
            if (idx < SCRATCH_TOT) {
                ((int*)g_cnt)[idx] = 0;
                ((float*)g_num)[idx] = 0.0f;
                ((float*)g_den)[idx] = 0.0f;
                ((unsigned long long*)g_packed)[idx] = 0ull;
            }
        }
    }
    __syncthreads();

    int n = blockIdx.x * blockDim.x + threadIdx.x;
    float res = 0.0f;
    if (n < NHITS) {
        float2 c = cc[n];
        float x = c.x, y = c.y;
        float q = g_q[n];
        float h = fmaf(x, x, y * y);
        unsigned long long XX = pk2(x, x), YY = pk2(y, y), HH = pk2(h, h);
        float acc0 = 0.0f, acc1 = 0.0f;
        const ulonglong2* A2 = (const ulonglong2*)sA;
        const ulonglong2* B2 = (const ulonglong2*)sB;
        #pragma unroll 8
        for (int p = 0; p < KCHUNK / 2; p += 2) {
            {
                ulonglong2 A = A2[p];
                ulonglong2 B = B2[p];
                unsigned long long tt = fma2_(A.y, YY, B.x);
                tt = fma2_(A.x, XX, tt);
                tt = add2_(tt, HH);
                float d2a, d2b; unpk2(tt, d2a, d2b);
                float da = sqrt_approx(d2a), db = sqrt_approx(d2b);
                float wa, wb; unpk2(B.y, wa, wb);
                acc0 = fmaf(wa, fminf(da, 1.0f), acc0);
                acc0 = fmaf(wb, fminf(db, 1.0f), acc0);
            }
            {
                ulonglong2 A = A2[p + 1];
                ulonglong2 B = B2[p + 1];
                unsigned long long tt = fma2_(A.y, YY, B.x);
                tt = fma2_(A.x, XX, tt);
                tt = add2_(tt, HH);
                float d2a, d2b; unpk2(tt, d2a, d2b);
                float da = sqrt_approx(d2a), db = sqrt_approx(d2b);
                float wa, wb; unpk2(B.y, wa, wb);
                acc1 = fmaf(wa, fminf(da, 1.0f), acc1);
                acc1 = fmaf(wb, fminf(db, 1.0f), acc1);
            }
        }
        // sum_k w*relu(1-d) = Wsum_chunk - sum_k w*min(d,1)
        res = (g_wsum[blockIdx.y] - (acc0 + acc1)) * q;
        int t = tIdx[n];
        if (t >= kbase && t < kbase + KCHUNK) {
            int j = t - kbase;
            int pr = j >> 1, hf = j & 1;
            float4 Af = sA[pr], Bf = sB[pr];
            float m2ox = hf ? Af.y : Af.x;
            float m2oy = hf ? Af.w : Af.z;
            float w    = hf ? Bf.w : Bf.z;
            float dx = fmaf(0.5f, m2ox, x);
            float dy = fmaf(0.5f, m2oy, y);
            float d2n = fmaf(dx, dx, dy * dy);
            float d = sqrt_approx(d2n + 1e-6f);
            res -= fmaxf(1.0f - d, 0.0f) * w * q;
            res = fmaf(d2n * g_attw[t], q, res);
        }
    }
    __shared__ float sr[8];
    float wv = warpSum(res);
    int lane = threadIdx.x & 31, wid = threadIdx.x >> 5;
    if (lane == 0) sr[wid] = wv;
    __syncthreads();
    __shared__ bool isLast;
    if (threadIdx.x == 0) isLast = false;
    if (wid == 0) {
        float v = (lane < 8) ? sr[lane] : 0.0f;
        v = warpSum(v);
        if (lane == 0) {
            atomicAdd(&g_scal[3], v);
            __threadfence();
            unsigned tk = atomicAdd(&g_ticket3, 1u);
            isLast = (tk == (unsigned)(TOTAL_P3_BLOCKS - 1));
        }
    }
    __syncthreads();
    if (isLast) {
        if (threadIdx.x == 0) {
            float inv = 1.0f / (g_scal[6] + EPSF);
            float total = (g_scal[3] + g_scal[4]) * inv
                        + g_scal[0] / (g_scal[1] + EPSF)
                        + 0.001f * g_scal[2] * (1.0f / ((float)NHITS * 2.0f));
            out[0] = total;
            g_ticket3 = 0;
        }
        __syncthreads();
        if (threadIdx.x < 8) {
            g_scal[threadIdx.x] = 0.0f;
            g_wsum[threadIdx.x] = 0.0f;
        }
    }
}

// ---------------- launch ----------------
extern "C" void kernel_launch(void* const* d_in, const int* in_sizes, int n_in,
                              void* d_out, int out_size)
{
    const float2* pb2   = (const float2*)d_in[0];
    const float4* cc4   = (const float4*)d_in[1];
    const float2* cc2   = (const float2*)d_in[1];
    const float2* pE2   = (const float2*)d_in[2];
    const float4* pPos4 = (const float4*)d_in[3];
    const float2* pT2   = (const float2*)d_in[4];
    const float4* pId4  = (const float4*)d_in[5];
    const int2*   tIdx2 = (const int2*)  d_in[6];
    const int*    tIdx  = (const int*)   d_in[6];
    const float2* tE2   = (const float2*)d_in[7];
    const float4* tPos4 = (const float4*)d_in[8];
    const float2* tT2   = (const float2*)d_in[9];
    float* out = (float*)d_out;

    k_phase1<<<NBX1, 256>>>(pb2, cc4, pE2, pPos4, pT2, pId4, tIdx2, tE2, tPos4, tT2, cc2);
    dim3 g3(NBX3, NCHUNK);
    k_phase3<<<g3, 256>>>(cc2, tIdx, out);
}